// round 12
// baseline (speedup 1.0000x reference)
#include <cuda_runtime.h>

// PoseNoiseTransform single-pass decoupled-lookback quaternion scan.
// Single kernel launch: epoch-encoded flags (no init/zeroing kernel).
// Local running prefixes staged in SMEM (inputs read from DRAM exactly once);
// lookback is per-thread (per-column flags, acquire/release), no block syncs.
//
//   q:     [TS, NS, 4] f32 unit quaternions (w,x,y,z)
//   noise: [TS-1, NS, 4] f32 uniform [0,1)
//   out:   [TS, NS, 4] f32
//
// out[0]   = q[0]
// q_dot[t] = (q[t+1] * conj(q[t])) * normalize((noise[t]-0.5)*[1,.05,.05,.05])
// out[i+1] = q_dot[i] * ... * q_dot[0] * q[0]
//
// Epoch protocol: g_vid is a persistent ticket counter (never reset). Each
// launch consumes exactly nblocks tickets, so epoch = vid / nblocks is
// uniform per launch and increments every graph replay. Flags are published
// as 2*epoch+1 (aggregate) / 2*epoch+2 (inclusive); values from previous
// epochs are <= 2*epoch and read as "not ready". No flag reset needed.

#define BLK 256
#define CHUNK 9           // SMEM = 256*9*16 = 36 KB -> 6 CTAs/SM (regs ~40 also allow 6)
#define NCH_MAX 232
#define NS_MAX 8192

// Scratch (device globals; no allocation allowed anywhere).
__device__ float4 g_agg[NCH_MAX * NS_MAX];          // per-chunk aggregate, per column
__device__ float4 g_inc[NCH_MAX * NS_MAX];          // per-chunk inclusive, per column
__device__ unsigned int g_flag[NCH_MAX * NS_MAX];   // epoch-encoded readiness
__device__ unsigned int g_vid;                      // persistent ticket counter

// Quaternion in float4: .x=w .y=x .z=y .w=z ; returns a*b (Hamilton)
__device__ __forceinline__ float4 qmul(float4 a, float4 b) {
    float aw = a.x, ax = a.y, ay = a.z, az = a.w;
    float bw = b.x, bx = b.y, by = b.z, bz = b.w;
    return make_float4(
        aw * bw - ax * bx - ay * by - az * bz,
        aw * bx + ax * bw + ay * bz - az * by,
        aw * by - ax * bz + ay * bw + az * bx,
        aw * bz + ax * by - ay * bx + az * bw);
}

__device__ __forceinline__ float4 qdot_step(float4 qnext, float4 qprev, float4 nz) {
    // rel = qnext * conj(qprev), conj signs folded
    float aw = qnext.x, ax = qnext.y, ay = qnext.z, az = qnext.w;
    float bw = qprev.x, bx = -qprev.y, by = -qprev.z, bz = -qprev.w;
    float4 rel = make_float4(
        aw * bw - ax * bx - ay * by - az * bz,
        aw * bx + ax * bw + ay * bz - az * by,
        aw * by - ax * bz + ay * bw + az * bx,
        aw * bz + ax * by - ay * bx + az * bw);

    // q_samp = normalize((nz - 0.5) * [1, .05, .05, .05])
    float sw = nz.x - 0.5f;
    float sx = (nz.y - 0.5f) * 0.05f;
    float sy = (nz.z - 0.5f) * 0.05f;
    float sz = (nz.w - 0.5f) * 0.05f;
    float d = sw * sw + sx * sx + sy * sy + sz * sz;
    float r = rsqrtf(d);
    r = r * (1.5f - 0.5f * d * r * r);   // Newton step -> full fp32 accuracy
    float4 samp = make_float4(sw * r, sx * r, sy * r, sz * r);

    return qmul(rel, samp);
}

__device__ __forceinline__ unsigned int ld_acquire(const unsigned int* p) {
    unsigned int v;
    asm volatile("ld.acquire.gpu.global.b32 %0, [%1];" : "=r"(v) : "l"(p) : "memory");
    return v;
}
__device__ __forceinline__ void st_release(unsigned int* p, unsigned int v) {
    asm volatile("st.release.gpu.global.b32 [%0], %1;" :: "l"(p), "r"(v) : "memory");
}

__global__ void __launch_bounds__(BLK) scan_kernel(
    const float4* __restrict__ q, const float4* __restrict__ noise,
    float4* __restrict__ out, int NS, int T, int CB, int NCH, unsigned int nblocks)
{
    __shared__ float4 spre[CHUNK][BLK];   // running LOCAL prefixes (own column only)
    __shared__ unsigned int s_vid;

    // Persistent ticket: block order == chunk order within this launch.
    if (threadIdx.x == 0) s_vid = atomicAdd(&g_vid, 1u);
    __syncthreads();
    unsigned int ticket = s_vid;
    unsigned int epoch  = ticket / nblocks;      // uniform across this launch
    unsigned int vid    = ticket % nblocks;      // 0..nblocks-1 in scheduling order
    unsigned int base   = 2u * epoch;            // flag base for this epoch

    int c  = (int)(vid / (unsigned)CB);
    int cb = (int)(vid % (unsigned)CB);
    int n  = cb * BLK + threadIdx.x;
    if (n >= NS) return;                  // no cross-thread deps -> safe to exit

    int t0 = c * CHUNK;
    int t1 = min(T, t0 + CHUNK);
    int len = t1 - t0;                    // 1..CHUNK

    // ---- Walk 1: running local prefix -> SMEM; A ends as chunk aggregate ----
    float4 A = make_float4(1.f, 0.f, 0.f, 0.f);
    {
        float4 qprev = q[(size_t)t0 * NS + n];
        #pragma unroll
        for (int i = 0; i < CHUNK; ++i) {
            if (i < len) {
                int t = t0 + i;
                float4 qn = q[(size_t)(t + 1) * NS + n];
                float4 nz = noise[(size_t)t * NS + n];
                float4 qd = qdot_step(qn, qprev, nz);
                A = qmul(qd, A);                  // local prefix qdot[i]*...*qdot[t0]
                spre[i][threadIdx.x] = A;
                qprev = qn;
            }
        }
    }

    // ---- Per-thread decoupled lookback (epoch-encoded per-column flags) ----
    float4 S = make_float4(1.f, 0.f, 0.f, 0.f);  // exclusive prefix P_{c-1}
    if (c > 0) {
        if (c < NCH - 1) {                        // last chunk's agg is never read
            g_agg[c * NS + n] = A;
            st_release(&g_flag[c * NS + n], base + 1u);  // release orders payload
        }

        int p = c - 1;
        while (true) {
            int s;
            int backoff = 16;
            while ((s = (int)(ld_acquire(&g_flag[p * NS + n]) - base)) <= 0) {
                __nanosleep(backoff);
                if (backoff < 256) backoff += backoff;
            }
            if (s >= 2) { S = qmul(S, g_inc[p * NS + n]); break; }
            S = qmul(S, g_agg[p * NS + n]);
            if (--p < 0) break;
        }
    }

    // ---- Publish inclusive P_c = A * P_{c-1} ----
    if (c < NCH - 1) {                    // last chunk's inclusive is never read
        float4 P = qmul(A, S);
        g_inc[c * NS + n] = P;
        st_release(&g_flag[c * NS + n], base + 2u);
    }

    // ---- Walk 2: out = local_prefix[i] * carry; fully independent per i ----
    float4 q0 = q[n];
    if (c == 0) out[n] = q0;              // out[0] = q[0]
    float4 carry = qmul(S, q0);           // P_{c-1} * q[0]
    #pragma unroll
    for (int i = 0; i < CHUNK; ++i) {
        if (i < len) {
            out[(size_t)(t0 + i + 1) * NS + n] = qmul(spre[i][threadIdx.x], carry);
        }
    }
}

extern "C" void kernel_launch(void* const* d_in, const int* in_sizes, int n_in,
                              void* d_out, int out_size)
{
    const float4* q     = (const float4*)d_in[0];
    const float4* noise = (const float4*)d_in[1];
    float4* out         = (float4*)d_out;

    int quats0 = in_sizes[0] / 4;          // TS*NS
    int quats1 = in_sizes[1] / 4;          // (TS-1)*NS
    int NS = quats0 - quats1;
    int TS = quats0 / NS;
    int T  = TS - 1;
    int nch = (T + CHUNK - 1) / CHUNK;     // chunks (<= NCH_MAX)
    int CB  = (NS + BLK - 1) / BLK;        // column-blocks
    unsigned int nblocks = (unsigned int)(nch * CB);

    scan_kernel<<<nblocks, BLK>>>(q, noise, out, NS, T, CB, nch, nblocks);
}

// round 15
// speedup vs baseline: 1.0193x; 1.0193x over previous
#include <cuda_runtime.h>

// PoseNoiseTransform single-pass decoupled-lookback quaternion scan.
// Single launch, epoch-encoded flags (no reset kernel). Local running
// prefixes staged in SMEM; per-thread lookback (per-column flags,
// acquire/release). Streaming cache hints (.cs) keep the 384 MB of
// once-touched data out of L2 so scratch/flags stay resident.
//
//   q:     [TS, NS, 4] f32 unit quaternions (w,x,y,z)
//   noise: [TS-1, NS, 4] f32 uniform [0,1)
//   out:   [TS, NS, 4] f32
//
// out[0]   = q[0]
// q_dot[t] = (q[t+1] * conj(q[t])) * normalize((noise[t]-0.5)*[1,.05,.05,.05])
// out[i+1] = q_dot[i] * ... * q_dot[0] * q[0]
//
// q[0] folding: chunk 0 publishes its inclusive as P_0 = A * q0, so every
// later chunk's lookback result S already contains q0 and is the carry
// directly. Only chunk-0 blocks ever read q[0].
//
// Epoch protocol: g_vid is a persistent ticket counter. Each launch consumes
// exactly nblocks tickets, so epoch = ticket / nblocks is uniform per launch
// and increments every graph replay. Flags publish as 2*epoch+{1,2}; stale
// values from earlier epochs read as "not ready". No flag zeroing needed.

#define BLK 256
#define CHUNK 11          // SMEM = 256*11*16 = 45056 B -> 5 CTAs/SM (best measured)
#define NCH_MAX 192
#define NS_MAX 8192

// Scratch (device globals; no allocation allowed anywhere).
__device__ float4 g_agg[NCH_MAX * NS_MAX];          // per-chunk aggregate, per column
__device__ float4 g_inc[NCH_MAX * NS_MAX];          // per-chunk inclusive (q0-folded)
__device__ unsigned int g_flag[NCH_MAX * NS_MAX];   // epoch-encoded readiness
__device__ unsigned int g_vid;                      // persistent ticket counter

// Quaternion in float4: .x=w .y=x .z=y .w=z ; returns a*b (Hamilton)
__device__ __forceinline__ float4 qmul(float4 a, float4 b) {
    float aw = a.x, ax = a.y, ay = a.z, az = a.w;
    float bw = b.x, bx = b.y, by = b.z, bz = b.w;
    return make_float4(
        aw * bw - ax * bx - ay * by - az * bz,
        aw * bx + ax * bw + ay * bz - az * by,
        aw * by - ax * bz + ay * bw + az * bx,
        aw * bz + ax * by - ay * bx + az * bw);
}

__device__ __forceinline__ float4 qdot_step(float4 qnext, float4 qprev, float4 nz) {
    // rel = qnext * conj(qprev), conj signs folded
    float aw = qnext.x, ax = qnext.y, ay = qnext.z, az = qnext.w;
    float bw = qprev.x, bx = -qprev.y, by = -qprev.z, bz = -qprev.w;
    float4 rel = make_float4(
        aw * bw - ax * bx - ay * by - az * bz,
        aw * bx + ax * bw + ay * bz - az * by,
        aw * by - ax * bz + ay * bw + az * bx,
        aw * bz + ax * by - ay * bx + az * bw);

    // q_samp = normalize((nz - 0.5) * [1, .05, .05, .05])
    float sw = nz.x - 0.5f;
    float sx = (nz.y - 0.5f) * 0.05f;
    float sy = (nz.z - 0.5f) * 0.05f;
    float sz = (nz.w - 0.5f) * 0.05f;
    float d = sw * sw + sx * sx + sy * sy + sz * sz;
    float r = rsqrtf(d);
    r = r * (1.5f - 0.5f * d * r * r);   // Newton step -> full fp32 accuracy
    float4 samp = make_float4(sw * r, sx * r, sy * r, sz * r);

    return qmul(rel, samp);
}

__device__ __forceinline__ unsigned int ld_acquire(const unsigned int* p) {
    unsigned int v;
    asm volatile("ld.acquire.gpu.global.b32 %0, [%1];" : "=r"(v) : "l"(p) : "memory");
    return v;
}
__device__ __forceinline__ void st_release(unsigned int* p, unsigned int v) {
    asm volatile("st.release.gpu.global.b32 [%0], %1;" :: "l"(p), "r"(v) : "memory");
}

__global__ void __launch_bounds__(BLK) scan_kernel(
    const float4* __restrict__ q, const float4* __restrict__ noise,
    float4* __restrict__ out, int NS, int T, int CB, int NCH, unsigned int nblocks)
{
    __shared__ float4 spre[CHUNK][BLK];   // running LOCAL prefixes (own column only)
    __shared__ unsigned int s_vid;

    // Persistent ticket: block order == chunk order within this launch.
    if (threadIdx.x == 0) s_vid = atomicAdd(&g_vid, 1u);
    __syncthreads();
    unsigned int ticket = s_vid;
    unsigned int epoch  = ticket / nblocks;      // uniform across this launch
    unsigned int vid    = ticket % nblocks;      // 0..nblocks-1 in scheduling order
    unsigned int base   = 2u * epoch;            // flag base for this epoch

    int c  = (int)(vid / (unsigned)CB);
    int cb = (int)(vid % (unsigned)CB);
    int n  = cb * BLK + threadIdx.x;
    if (n >= NS) return;                  // no cross-thread deps -> safe to exit

    int t0 = c * CHUNK;
    int t1 = min(T, t0 + CHUNK);
    int len = t1 - t0;                    // 1..CHUNK

    // ---- Walk 1: running local prefix -> SMEM; A ends as chunk aggregate ----
    // Streaming loads (.cs): q/noise are never re-read, keep them out of L2.
    float4 A = make_float4(1.f, 0.f, 0.f, 0.f);
    {
        float4 qprev = __ldcs(&q[(size_t)t0 * NS + n]);
        #pragma unroll
        for (int i = 0; i < CHUNK; ++i) {
            if (i < len) {
                int t = t0 + i;
                float4 qn = __ldcs(&q[(size_t)(t + 1) * NS + n]);
                float4 nz = __ldcs(&noise[(size_t)t * NS + n]);
                float4 qd = qdot_step(qn, qprev, nz);
                A = qmul(qd, A);                  // local prefix qdot[i]*...*qdot[t0]
                spre[i][threadIdx.x] = A;
                qprev = qn;
            }
        }
    }

    // ---- Per-thread decoupled lookback (epoch-encoded per-column flags) ----
    // S resolves to P_{c-1} * ... which includes q0 (folded at chunk 0).
    float4 S;
    if (c > 0) {
        S = make_float4(1.f, 0.f, 0.f, 0.f);
        if (c < NCH - 1) {                        // last chunk's agg is never read
            g_agg[c * NS + n] = A;
            st_release(&g_flag[c * NS + n], base + 1u);  // release orders payload
        }

        int p = c - 1;
        while (true) {
            int s;
            int backoff = 16;
            while ((s = (int)(ld_acquire(&g_flag[p * NS + n]) - base)) <= 0) {
                __nanosleep(backoff);
                if (backoff < 256) backoff += backoff;
            }
            if (s >= 2) { S = qmul(S, g_inc[p * NS + n]); break; }
            S = qmul(S, g_agg[p * NS + n]);
            if (--p < 0) break;   // unreachable: chunk 0 only ever publishes flag 2
        }
    } else {
        S = __ldg(&q[n]);                 // chunk 0: carry is q0 itself
        __stcs(&out[n], S);               // out[0] = q[0]
    }

    // ---- Publish inclusive P_c = A * S (q0 folded in) ----
    if (c < NCH - 1) {                    // last chunk's inclusive is never read
        float4 P = qmul(A, S);
        g_inc[c * NS + n] = P;
        st_release(&g_flag[c * NS + n], base + 2u);
    }

    // ---- Walk 2: out = local_prefix[i] * S; fully independent per i ----
    #pragma unroll
    for (int i = 0; i < CHUNK; ++i) {
        if (i < len) {
            __stcs(&out[(size_t)(t0 + i + 1) * NS + n], qmul(spre[i][threadIdx.x], S));
        }
    }
}

extern "C" void kernel_launch(void* const* d_in, const int* in_sizes, int n_in,
                              void* d_out, int out_size)
{
    const float4* q     = (const float4*)d_in[0];
    const float4* noise = (const float4*)d_in[1];
    float4* out         = (float4*)d_out;

    int quats0 = in_sizes[0] / 4;          // TS*NS
    int quats1 = in_sizes[1] / 4;          // (TS-1)*NS
    int NS = quats0 - quats1;
    int TS = quats0 / NS;
    int T  = TS - 1;
    int nch = (T + CHUNK - 1) / CHUNK;     // chunks (<= NCH_MAX)
    int CB  = (NS + BLK - 1) / BLK;        // column-blocks
    unsigned int nblocks = (unsigned int)(nch * CB);

    scan_kernel<<<nblocks, BLK>>>(q, noise, out, NS, T, CB, nch, nblocks);
}